// round 10
// baseline (speedup 1.0000x reference)
#include <cuda_runtime.h>
#include <cuda_fp16.h>
#include <cstdint>

// ---------------- problem dims (fixed) ----------------
#define BATCH   32
#define RDIM    5
#define NNODES  1024
#define DDIM    256
#define HDIM    256
#define MTOT    (BATCH * NNODES)    // 32768

// ---------------- tiling ----------------
#define TM      64                  // CTA M tile (one CTA per tile_m -> adj read once)
#define TH      256                 // CTA H tile (full H)
#define NTHREADS 512                // 16 warps: wm in {0,1}, wh in {0..7}, warp tile 32x32

// A: 64 rows x 256 cols fp16, row stride 528 B; hi at 0, lo at +33792
#define SAB     528
#define ABUF    (TM * SAB)          // 33792
#define SM_ALO  ABUF
// w0 quarter-K chunk: 256 rows x 64 cols fp16, stride 144 B; hi + lo
#define QROW    144
#define QSZ     (TH * QROW)         // 36864
// relation half-K chunk: 256 rows x 128 cols fp16, stride 272 B (hi only)
#define RROW    272
#define SLOT    (2 * QSZ)           // 73728 (fits rel chunk 69632 too)
#define SM_B0   (2 * ABUF)          // 67584
#define SM_SCL  (SM_B0 + 2 * SLOT)  // 215040
#define SM_TOTAL (SM_SCL + RDIM * TM * 4 + 256)  // ~216576

#define NCHUNK  14                  // c0..3: w0 quarter-K (3-pass); c4..13: 5 relations x 2 half-K

// ---------------- device scratch ----------------
__device__ __align__(16) __half g_nhi[MTOT * DDIM];        // nodes fp16 hi [m][d]
__device__ __align__(16) __half g_nlo[MTOT * DDIM];        // nodes fp16 lo
__device__ __align__(16) __half g_whi[6 * HDIM * DDIM];    // [g][h][d] fp16 hi (g=0 is w0)
__device__ __align__(16) __half g_wlo[HDIM * DDIM];        // w0 fp16 lo

// ---------------- helpers ----------------
__device__ __forceinline__ uint32_t smem_u32(const void* p) {
    uint32_t a;
    asm("{ .reg .u64 t; cvta.to.shared.u64 t, %1; cvt.u32.u64 %0, t; }" : "=r"(a) : "l"(p));
    return a;
}
__device__ __forceinline__ void ldm4(uint32_t* r, uint32_t addr) {
    asm volatile("ldmatrix.sync.aligned.m8n8.x4.shared.b16 {%0,%1,%2,%3}, [%4];"
                 : "=r"(r[0]), "=r"(r[1]), "=r"(r[2]), "=r"(r[3]) : "r"(addr));
}
__device__ __forceinline__ void mma16816(float* c, const uint32_t* a,
                                         uint32_t b0, uint32_t b1) {
    asm volatile("mma.sync.aligned.m16n8k16.row.col.f32.f16.f16.f32 "
                 "{%0,%1,%2,%3}, {%4,%5,%6,%7}, {%8,%9}, {%0,%1,%2,%3};"
                 : "+f"(c[0]), "+f"(c[1]), "+f"(c[2]), "+f"(c[3])
                 : "r"(a[0]), "r"(a[1]), "r"(a[2]), "r"(a[3]), "r"(b0), "r"(b1));
}
__device__ __forceinline__ void cpasync16(uint32_t dst, const void* src) {
    asm volatile("cp.async.cg.shared.global [%0], [%1], 16;" :: "r"(dst), "l"(src));
}
template<int N> __device__ __forceinline__ void cpwait() {
    asm volatile("cp.async.wait_group %0;" :: "n"(N));
}
#define CP_COMMIT() asm volatile("cp.async.commit_group;" ::: "memory")

__device__ __forceinline__ uint32_t hscale(uint32_t v, uint32_t s2) {
    __half2 r = __hmul2(*reinterpret_cast<__half2*>(&v),
                        *reinterpret_cast<__half2*>(&s2));
    return *reinterpret_cast<uint32_t*>(&r);
}

// ---------------- kernel 1: nodes -> fp16 hi/lo ----------------
__global__ void prep_nodes_kernel(const float* __restrict__ nodes) {
    int idx = blockIdx.x * blockDim.x + threadIdx.x;    // float4 index
    if (idx >= MTOT * DDIM / 4) return;
    float4 v = reinterpret_cast<const float4*>(nodes)[idx];
    __half h0 = __float2half_rn(v.x), h1 = __float2half_rn(v.y);
    __half h2 = __float2half_rn(v.z), h3 = __float2half_rn(v.w);
    __half l0 = __float2half_rn(v.x - __half2float(h0));
    __half l1 = __float2half_rn(v.y - __half2float(h1));
    __half l2 = __float2half_rn(v.z - __half2float(h2));
    __half l3 = __float2half_rn(v.w - __half2float(h3));
    __half2 hA = {h0, h1}, hB = {h2, h3}, lA = {l0, l1}, lB = {l2, l3};
    uint2 hp = make_uint2(*reinterpret_cast<uint32_t*>(&hA), *reinterpret_cast<uint32_t*>(&hB));
    uint2 lp = make_uint2(*reinterpret_cast<uint32_t*>(&lA), *reinterpret_cast<uint32_t*>(&lB));
    reinterpret_cast<uint2*>(g_nhi)[idx] = hp;
    reinterpret_cast<uint2*>(g_nlo)[idx] = lp;
}

// ---------------- kernel 2: weights -> stacked [g][h][d] fp16 ------------
__global__ void prep_w_kernel(const float* __restrict__ w0,
                              const float* __restrict__ wr) {
    int idx = blockIdx.x * blockDim.x + threadIdx.x;
    if (idx >= 6 * HDIM * DDIM) return;
    int g = idx / (HDIM * DDIM);
    int r = idx % (HDIM * DDIM);      // = h*DDIM + d
    float v = (g == 0) ? w0[r] : wr[(g - 1) * HDIM * DDIM + r];
    __half h = __float2half_rn(v);
    g_whi[idx] = h;
    if (g == 0) g_wlo[r] = __float2half_rn(v - __half2float(h));
}

// ---------------- kernel 3: fused rowsum + multi-GEMM --------------------
// grid (512), 512 threads. Each CTA owns rows [64*bx, 64*bx+64) and full H.
// c0..3: w0 quarter-K chunks, 3-pass fp16 hi/lo -> run.
// c4..13: relation (c-4)/2, half-K chunks, A-fragments pre-scaled by s(g,m).
// Row-sums (5x64 rows) computed in-kernel: 10 slices of 32 rows at chunk
// tops, alternating warp halves; scales land in smem >=2 chunks before use.
__global__ __launch_bounds__(NTHREADS, 1) void gemm_fused_kernel(
        const float* __restrict__ adj, float* __restrict__ out) {
    extern __shared__ char smem[];
    const uint32_t sb = smem_u32(smem);
    float* s_scl = reinterpret_cast<float*>(smem + SM_SCL);   // [5][64]
    const int tid  = threadIdx.x;
    const int wid  = tid >> 5;
    const int lane = tid & 31;
    const int wh = wid & 7;             // 0..7 -> h block of 32
    const int wm = wid >> 3;            // 0..1 -> m block of 32
    const int tile_m = blockIdx.x * TM;

    // ---- async-stage A hi/lo: [64 x 256] fp16 (group 0) ----
    #pragma unroll
    for (int i = tid; i < TM * 32; i += NTHREADS) {
        int row = i >> 5;
        int cq  = i & 31;
        size_t src = (size_t)(tile_m + row) * DDIM + cq * 8;
        uint32_t d = sb + (uint32_t)row * SAB + cq * 16;
        cpasync16(d, &g_nhi[src]);
        cpasync16(d + SM_ALO, &g_nlo[src]);
    }
    CP_COMMIT();

    // ---- chunk prefetch ----
    auto stage_chunk = [&](int stage, int c) {
        uint32_t base = sb + SM_B0 + (uint32_t)stage * SLOT;
        if (c < 4) {
            // w0 quarter-K: 256 h-rows x 64 cols, hi+lo
            #pragma unroll
            for (int i = tid; i < TH * 8; i += NTHREADS) {
                int row = i >> 3;
                int cq  = i & 7;
                size_t src = (size_t)row * DDIM + c * 64 + cq * 8;
                uint32_t d = base + (uint32_t)row * QROW + cq * 16;
                cpasync16(d, &g_whi[src]);
                cpasync16(d + QSZ, &g_wlo[src]);
            }
        } else {
            // relation half-K: 256 h-rows x 128 cols, hi only
            int g  = 1 + ((c - 4) >> 1);
            int kh = (c - 4) & 1;
            #pragma unroll
            for (int i = tid; i < TH * 16; i += NTHREADS) {
                int row = i >> 4;
                int cq  = i & 15;
                size_t src = ((size_t)g * HDIM + row) * DDIM + kh * 128 + cq * 8;
                uint32_t d = base + (uint32_t)row * RROW + cq * 16;
                cpasync16(d, &g_whi[src]);
            }
        }
        CP_COMMIT();
    };

    stage_chunk(0, 0);      // group 1

    // ---- per-thread ldmatrix base offsets (same micro-layout as before) --
    const uint32_t aRow = (uint32_t)(wm * 32 + (lane & 15)) * SAB + (lane >> 4) * 16;
    const uint32_t aHi0 = sb + aRow;
    const uint32_t aHi1 = aHi0 + 16 * SAB;
    const uint32_t aLo0 = sb + SM_ALO + aRow;
    const uint32_t aLo1 = aLo0 + 16 * SAB;
    const int n_loc  = (lane & 7) + ((lane >> 4) << 3);
    const int k_half = (lane >> 3) & 1;
    const uint32_t bRowQ = (uint32_t)(wh * 32 + n_loc) * QROW + (uint32_t)k_half * 16;
    const uint32_t bRowR = (uint32_t)(wh * 32 + n_loc) * RROW + (uint32_t)k_half * 16;

    float run[2][4][4];
    #pragma unroll
    for (int mi = 0; mi < 2; mi++)
        #pragma unroll
        for (int ni = 0; ni < 4; ni++)
            #pragma unroll
            for (int q = 0; q < 4; q++) run[mi][ni][q] = 0.0f;

    #pragma unroll 1
    for (int c = 0; c < NCHUNK; c++) {
        if (c + 1 < NCHUNK) {
            stage_chunk((c + 1) & 1, c + 1);
            cpwait<1>();
        } else {
            cpwait<0>();
        }
        __syncthreads();

        // ---- rowsum slice: 32 rows, alternating 256-thread halves ----
        if (c < 10 && (tid >> 8) == (c & 1)) {
            int trs  = tid & 255;
            int ridx = c * 32 + (trs >> 3);       // 0..319
            int sub  = trs & 7;
            int grel = ridx >> 6;                 // relation 0..4
            int lr   = ridx & 63;
            int m = tile_m + lr;
            int b = m >> 10, n = m & 1023;
            const float4* rp = reinterpret_cast<const float4*>(adj)
                             + (size_t)((b * RDIM + grel) * NNODES + n) * 256;
            float s = 0.0f;
            #pragma unroll 8
            for (int j = 0; j < 32; j++) {
                float4 v = __ldcs(&rp[sub + j * 8]);
                s += (v.x + v.y) + (v.z + v.w);
            }
            s += __shfl_xor_sync(0xffffffffu, s, 4);
            s += __shfl_xor_sync(0xffffffffu, s, 2);
            s += __shfl_xor_sync(0xffffffffu, s, 1);
            if (sub == 0) {
                if (s == 0.0f) s = 1.0f;
                s_scl[grel * 64 + lr] = 1.0f / s;
            }
        }

        const uint32_t stb = sb + SM_B0 + (uint32_t)(c & 1) * SLOT;

        if (c < 4) {
            // ---- w0 quarter-K: 3-pass hi/lo into run ----
            const uint32_t aq = (uint32_t)c * 128;     // 64 cols * 2B
            const uint32_t bH = stb + bRowQ;
            const uint32_t bL = bH + QSZ;
            #pragma unroll
            for (int kc = 0; kc < 4; kc++) {
                const uint32_t ko = (uint32_t)kc * 32;
                uint32_t ah0[4], ah1[4], al0[4], al1[4];
                uint32_t bh0[4], bh1[4], bl0[4], bl1[4];
                ldm4(ah0, aHi0 + aq + ko);
                ldm4(ah1, aHi1 + aq + ko);
                ldm4(bh0, bH + ko);
                ldm4(bh1, bH + 16 * QROW + ko);
                ldm4(al0, aLo0 + aq + ko);
                ldm4(al1, aLo1 + aq + ko);
                ldm4(bl0, bL + ko);
                ldm4(bl1, bL + 16 * QROW + ko);
                // hi*hi
                mma16816(run[0][0], ah0, bh0[0], bh0[1]);
                mma16816(run[0][1], ah0, bh0[2], bh0[3]);
                mma16816(run[0][2], ah0, bh1[0], bh1[1]);
                mma16816(run[0][3], ah0, bh1[2], bh1[3]);
                mma16816(run[1][0], ah1, bh0[0], bh0[1]);
                mma16816(run[1][1], ah1, bh0[2], bh0[3]);
                mma16816(run[1][2], ah1, bh1[0], bh1[1]);
                mma16816(run[1][3], ah1, bh1[2], bh1[3]);
                // hi*lo
                mma16816(run[0][0], ah0, bl0[0], bl0[1]);
                mma16816(run[0][1], ah0, bl0[2], bl0[3]);
                mma16816(run[0][2], ah0, bl1[0], bl1[1]);
                mma16816(run[0][3], ah0, bl1[2], bl1[3]);
                mma16816(run[1][0], ah1, bl0[0], bl0[1]);
                mma16816(run[1][1], ah1, bl0[2], bl0[3]);
                mma16816(run[1][2], ah1, bl1[0], bl1[1]);
                mma16816(run[1][3], ah1, bl1[2], bl1[3]);
                // lo*hi
                mma16816(run[0][0], al0, bh0[0], bh0[1]);
                mma16816(run[0][1], al0, bh0[2], bh0[3]);
                mma16816(run[0][2], al0, bh1[0], bh1[1]);
                mma16816(run[0][3], al0, bh1[2], bh1[3]);
                mma16816(run[1][0], al1, bh0[0], bh0[1]);
                mma16816(run[1][1], al1, bh0[2], bh0[3]);
                mma16816(run[1][2], al1, bh1[0], bh1[1]);
                mma16816(run[1][3], al1, bh1[2], bh1[3]);
            }
        } else {
            // ---- relation half-K: pre-scaled A fragments, 1-pass ----
            const int rel = (c - 4) >> 1;
            const int kh  = (c - 4) & 1;
            // per-thread scales for its 4 fragment rows (from smem)
            uint32_t s2[4];
            #pragma unroll
            for (int j = 0; j < 4; j++) {
                float s = s_scl[rel * 64 + wm * 32 + (lane >> 2) + j * 8];
                __half2 h = __float2half2_rn(s);
                s2[j] = *reinterpret_cast<uint32_t*>(&h);
            }
            const uint32_t aq = (uint32_t)kh * 256;    // 128 cols * 2B
            const uint32_t bB = stb + bRowR;
            #pragma unroll 4
            for (int kc = 0; kc < 8; kc++) {
                const uint32_t ko = (uint32_t)kc * 32;
                uint32_t a0[4], a1[4], b0[4], b1[4];
                ldm4(a0, aHi0 + aq + ko);
                ldm4(a1, aHi1 + aq + ko);
                ldm4(b0, bB + ko);
                ldm4(b1, bB + 16 * RROW + ko);
                // scale A by per-row s(g,m): regs {0,2} row j, {1,3} row j+1
                a0[0] = hscale(a0[0], s2[0]);  a0[2] = hscale(a0[2], s2[0]);
                a0[1] = hscale(a0[1], s2[1]);  a0[3] = hscale(a0[3], s2[1]);
                a1[0] = hscale(a1[0], s2[2]);  a1[2] = hscale(a1[2], s2[2]);
                a1[1] = hscale(a1[1], s2[3]);  a1[3] = hscale(a1[3], s2[3]);
                mma16816(run[0][0], a0, b0[0], b0[1]);
                mma16816(run[0][1], a0, b0[2], b0[3]);
                mma16816(run[0][2], a0, b1[0], b1[1]);
                mma16816(run[0][3], a0, b1[2], b1[3]);
                mma16816(run[1][0], a1, b0[0], b0[1]);
                mma16816(run[1][1], a1, b0[2], b0[3]);
                mma16816(run[1][2], a1, b1[0], b1[1]);
                mma16816(run[1][3], a1, b1[2], b1[3]);
            }
        }
        __syncthreads();    // stage (c&1) reusable at c+1
    }

    // ---- epilogue ----
    #pragma unroll
    for (int mi = 0; mi < 2; mi++) {
        int rowA = tile_m + wm * 32 + mi * 16 + (lane >> 2);
        #pragma unroll
        for (int ni = 0; ni < 4; ni++) {
            int col = wh * 32 + ni * 8 + (lane & 3) * 2;
            *reinterpret_cast<float2*>(&out[(size_t)rowA * HDIM + col]) =
                make_float2(run[mi][ni][0], run[mi][ni][1]);
            *reinterpret_cast<float2*>(&out[(size_t)(rowA + 8) * HDIM + col]) =
                make_float2(run[mi][ni][2], run[mi][ni][3]);
        }
    }
}

// ---------------- launch ----------------
extern "C" void kernel_launch(void* const* d_in, const int* in_sizes, int n_in,
                              void* d_out, int out_size) {
    const float* nodes = (const float*)d_in[0];
    const float* adj   = (const float*)d_in[1];
    const float* w0    = (const float*)d_in[2];
    const float* wr    = (const float*)d_in[3];
    float* out = (float*)d_out;

    cudaFuncSetAttribute(gemm_fused_kernel,
                         cudaFuncAttributeMaxDynamicSharedMemorySize, SM_TOTAL);

    prep_nodes_kernel<<<(MTOT * DDIM / 4 + 255) / 256, 256>>>(nodes);
    prep_w_kernel<<<(6 * HDIM * DDIM + 255) / 256, 256>>>(w0, wr);
    gemm_fused_kernel<<<MTOT / TM, NTHREADS, SM_TOTAL>>>(adj, out);
}